// round 14
// baseline (speedup 1.0000x reference)
#include <cuda_runtime.h>
#include <math.h>

#define TABLE_SIZE 524288
#define NUM_LEVELS 16
#define N_POINTS   1048576
#define TBL_TOTAL  (TABLE_SIZE * NUM_LEVELS)   // 8388608
#define HMASK      (TABLE_SIZE - 1)
#define P2         2654435761u
#define P3         805459861u

#define MORT_BITS  5
#define NBUCK      32768    // 2^(3*MORT_BITS)

#define AUX_BLOCKS 1184     // 148 SMs x 8 — all co-resident at occ 8
// Repack in float4-quads (4 table elems / iter): 2,097,152 quads total.
#define Q_A        1310720  // phase 1: 62.5%
#define Q_B        786432   // phase 2: 37.5%

// Static scratch (allocation-guard safe; zero-initialized at load):
__device__ float2 g_tbl[TBL_TOTAL];      // 64 MB feature-interleaved table
__device__ float4 g_xs[N_POINTS];        // 16 MB sorted points (.w = orig idx)
__device__ int    g_hist[NBUCK];         // histogram (zeroed in phase 2)
__device__ int    g_cursor[NBUCK];       // chunk-relative exclusive scan -> cursor
__device__ int    g_bsum[32];            // per-chunk totals
__device__ int           g_barcnt;       // grid barrier (self-resetting)
__device__ volatile int  g_bargen;       // generation (monotonic across replays)

struct ScalArr { float s[NUM_LEVELS]; };

// ---------------------------------------------------------------------------
// Software grid barrier: all AUX_BLOCKS are co-resident by construction.
// ---------------------------------------------------------------------------
__device__ __forceinline__ void grid_sync() {
    __syncthreads();
    if (threadIdx.x == 0) {
        __threadfence();
        int my = g_bargen;
        int old = atomicAdd(&g_barcnt, 1);
        if (old == AUX_BLOCKS - 1) {
            g_barcnt = 0;
            __threadfence();
            g_bargen = my + 1;
        } else {
            while (g_bargen == my) __nanosleep(64);
        }
    }
    __syncthreads();
}

// Repack 4 consecutive table elements (one float4 per plane -> two float4s).
__device__ __forceinline__ void repack_quad(const float* __restrict__ ht, int q) {
    int i4 = q * 4;
    float4 a = __ldg((const float4*)(ht + i4));
    float4 b = __ldg((const float4*)(ht + TBL_TOTAL + i4));
    float4* dst = (float4*)&g_tbl[i4];
    dst[0] = make_float4(a.x, b.x, a.y, b.y);
    dst[1] = make_float4(a.z, b.z, a.w, b.w);
}

// ---------------------------------------------------------------------------
// Morton bucket (5 bits/dim -> 15-bit code)
// ---------------------------------------------------------------------------
__device__ __forceinline__ unsigned mort5(unsigned v) {
    unsigned m = 0;
    #pragma unroll
    for (int b = 0; b < MORT_BITS; ++b) m |= ((v >> b) & 1u) << (3 * b);
    return m;
}

__device__ __forceinline__ unsigned bucket_of(float x, float y, float z) {
    unsigned ix = min(31u, (unsigned)(int)(x * 32.0f));
    unsigned iy = min(31u, (unsigned)(int)(y * 32.0f));
    unsigned iz = min(31u, (unsigned)(int)(z * 32.0f));
    return mort5(ix) | (mort5(iy) << 1) | (mort5(iz) << 2);
}

// ---------------------------------------------------------------------------
// Persistent aux kernel: hist -> scan -> scatter; repack in phases 1+2
// (R11 schedule — phase-3 repack contends with scatter, proven in R13).
// ---------------------------------------------------------------------------
__global__ __launch_bounds__(256, 8) void aux_kernel(const float* __restrict__ x,
                                                     const float* __restrict__ ht) {
    const int t    = threadIdx.x;
    const int gtid = blockIdx.x * 256 + t;
    const int GT   = AUX_BLOCKS * 256;

    __shared__ int s_w[8];
    __shared__ int s_boff[32];

    // ---- Phase 1: histogram + repack A ----
    for (int n = gtid; n < N_POINTS; n += GT) {
        float vx = x[3 * n + 0], vy = x[3 * n + 1], vz = x[3 * n + 2];
        atomicAdd(&g_hist[bucket_of(vx, vy, vz)], 1);
    }
    for (int q = gtid; q < Q_A; q += GT) repack_quad(ht, q);

    grid_sync();

    // ---- Phase 2: 32 blocks scan their 1024-bucket chunk; rest repack B ----
    if (blockIdx.x < 32) {
        int c = blockIdx.x;
        int base = c * 1024 + t * 4;
        int4 v = __ldcg((const int4*)&g_hist[base]);
        int tot = v.x + v.y + v.z + v.w;

        int lane = t & 31, w = t >> 5;
        int s = tot;
        #pragma unroll
        for (int off = 1; off < 32; off <<= 1) {
            int u = __shfl_up_sync(0xFFFFFFFF, s, off);
            if (lane >= off) s += u;
        }
        if (lane == 31) s_w[w] = s;
        __syncthreads();
        if (w == 0 && lane < 8) {
            int v8 = s_w[lane];
            int s8 = v8;
            #pragma unroll
            for (int off = 1; off < 8; off <<= 1) {
                int u = __shfl_up_sync(0xFF, s8, off);
                if (lane >= off) s8 += u;
            }
            s_w[lane] = s8 - v8;
        }
        __syncthreads();
        int run = s_w[w] + (s - tot);

        int4 cu;
        cu.x = run; run += v.x;
        cu.y = run; run += v.y;
        cu.z = run; run += v.z;
        cu.w = run; run += v.w;
        *(int4*)&g_cursor[base] = cu;
        *(int4*)&g_hist[base]   = make_int4(0, 0, 0, 0);
        if (t == 255) g_bsum[c] = run;
    } else {
        int gtid2 = (blockIdx.x - 32) * 256 + t;
        int GT2   = (AUX_BLOCKS - 32) * 256;
        for (int q = gtid2; q < Q_B; q += GT2) repack_quad(ht, Q_A + q);
    }

    grid_sync();

    // ---- Phase 3: inline boff scan + scatter ----
    if (t < 32) {
        int v = __ldcg(&g_bsum[t]);
        int s = v;
        #pragma unroll
        for (int off = 1; off < 32; off <<= 1) {
            int u = __shfl_up_sync(0xFFFFFFFF, s, off);
            if (t >= off) s += u;
        }
        s_boff[t] = s - v;
    }
    __syncthreads();

    for (int n = gtid; n < N_POINTS; n += GT) {
        float vx = x[3 * n + 0], vy = x[3 * n + 1], vz = x[3 * n + 2];
        unsigned b = bucket_of(vx, vy, vz);
        int pos = s_boff[b >> 10] + atomicAdd(&g_cursor[b], 1);
        g_xs[pos] = make_float4(vx, vy, vz, __int_as_float(n));
    }
}

// ---------------------------------------------------------------------------
// Scrambled weight: fracflat[k] = frac( coord[k%3] * scaling[k/3] )
// ---------------------------------------------------------------------------
__device__ __forceinline__ float fracw(float vx, float vy, float vz,
                                       const float* __restrict__ s, int k) {
    int d = k % 3;
    float v = (d == 0) ? vx : ((d == 1) ? vy : vz);
    float t = v * s[k / 3];
    return t - floorf(t);
}

// ---------------------------------------------------------------------------
// Paired x-corner gather (R11 proven form). PRIMES[0]==1, so the two
// x-corners hash to i0 = fx^m, i1 = (fx+1)^m; when fx is even they are the
// two halves of ONE 16B-aligned float4 -> one load / one sector.
// ---------------------------------------------------------------------------
__device__ __forceinline__ void ld_xpair(const float2* __restrict__ tbl,
                                         unsigned fx, unsigned cx, unsigned m,
                                         float2& Ff, float2& Fc) {
    unsigned i0 = (fx ^ m) & HMASK;
    unsigned i1 = (cx ^ m) & HMASK;
    float4 q = __ldg((const float4*)(tbl + (i0 & ~1u)));
    float2 lo = make_float2(q.x, q.y);
    float2 hi = make_float2(q.z, q.w);
    Ff = (i0 & 1u) ? hi : lo;
    if ((i0 ^ i1) <= 1u) {
        Fc = (i1 & 1u) ? hi : lo;          // same aligned pair: free
    } else {
        Fc = __ldg(tbl + i1);              // predicated second load (~50% lanes)
    }
}

// One level: 4 paired gathers + scrambled trilinear blend -> 2 floats.
__device__ __forceinline__ void enc_level(float vx, float vy, float vz,
                                          const ScalArr& sc, int L,
                                          float& out0, float& out1) {
    float s  = sc.s[L];
    float sx = vx * s, sy = vy * s, sz = vz * s;

    unsigned fx = (unsigned)(int)floorf(sx);
    unsigned cx = (unsigned)(int)ceilf(sx);
    unsigned fy = (unsigned)(int)floorf(sy);
    unsigned cy = (unsigned)(int)ceilf(sy);
    unsigned fz = (unsigned)(int)floorf(sz);
    unsigned cz = (unsigned)(int)ceilf(sz);

    unsigned hyf = fy * P2, hyc = cy * P2;
    unsigned hzf = fz * P3, hzc = cz * P3;

    const float2* __restrict__ tbl = g_tbl + (size_t)L * TABLE_SIZE;

    float2 F0, F1, F2, F3, F4, F5, F6, F7;
    ld_xpair(tbl, fx, cx, hyc ^ hzc, F3, F0);
    ld_xpair(tbl, fx, cx, hyc ^ hzf, F5, F1);
    ld_xpair(tbl, fx, cx, hyf ^ hzc, F6, F2);
    ld_xpair(tbl, fx, cx, hyf ^ hzf, F7, F4);

    float wx = fracw(vx, vy, vz, sc.s, L);
    float wy = fracw(vx, vy, vz, sc.s, 16 + L);
    float wz = fracw(vx, vy, vz, sc.s, 32 + L);
    float qx = 1.0f - wx, qy = 1.0f - wy, qz = 1.0f - wz;

    {
        float f03 = F0.x * wx + F3.x * qx;
        float f12 = F1.x * wx + F2.x * qx;
        float f56 = F5.x * wx + F6.x * qx;
        float f47 = F4.x * wx + F7.x * qx;
        float a   = f03 * wy + f12 * qy;
        float b   = f47 * wy + f56 * qy;
        out0 = a * wz + b * qz;
    }
    {
        float f03 = F0.y * wx + F3.y * qx;
        float f12 = F1.y * wx + F2.y * qx;
        float f56 = F5.y * wx + F6.y * qx;
        float f47 = F4.y * wx + F7.y * qx;
        float a   = f03 * wy + f12 * qy;
        float b   = f47 * wy + f56 * qy;
        out1 = a * wz + b * qz;
    }
}

// ---------------------------------------------------------------------------
// Main encoding kernel: one thread per (Morton-sorted) point.
// ---------------------------------------------------------------------------
__global__ __launch_bounds__(256, 4) void hashenc_kernel(
    float* __restrict__ out,
    ScalArr sc)
{
    int n = blockIdx.x * blockDim.x + threadIdx.x;

    float4 p = g_xs[n];
    float vx = p.x, vy = p.y, vz = p.z;
    int orig = __float_as_int(p.w);

    float4* o = (float4*)(out + (size_t)orig * (2 * NUM_LEVELS));

    #pragma unroll
    for (int Lp = 0; Lp < NUM_LEVELS / 2; ++Lp) {
        float4 r;
        enc_level(vx, vy, vz, sc, 2 * Lp + 0, r.x, r.y);
        enc_level(vx, vy, vz, sc, 2 * Lp + 1, r.z, r.w);
        o[Lp] = r;
    }
}

// ---------------------------------------------------------------------------
// Host: replicate numpy's SCALINGS bit-for-bit with double libm.
// ---------------------------------------------------------------------------
static void compute_scalings(ScalArr& a) {
    double growth = exp((log(2048.0) - log(16.0)) / 15.0);
    for (int l = 0; l < NUM_LEVELS; ++l)
        a.s[l] = (float)floor(16.0 * pow(growth, (double)l));
}

extern "C" void kernel_launch(void* const* d_in, const int* in_sizes, int n_in,
                              void* d_out, int out_size) {
    const float* x  = (const float*)d_in[0];
    const float* ht = (const float*)d_in[1];
    float* out = (float*)d_out;

    ScalArr sc;
    compute_scalings(sc);

    aux_kernel<<<AUX_BLOCKS, 256>>>(x, ht);
    hashenc_kernel<<<N_POINTS / 256, 256>>>(out, sc);
}

// round 15
// speedup vs baseline: 1.0164x; 1.0164x over previous
#include <cuda_runtime.h>
#include <math.h>

#define TABLE_SIZE 524288
#define NUM_LEVELS 16
#define N_POINTS   1048576
#define TBL_TOTAL  (TABLE_SIZE * NUM_LEVELS)   // 8388608
#define HMASK      (TABLE_SIZE - 1)
#define P2         2654435761u
#define P3         805459861u

#define MORT_BITS  5
#define NBUCK      32768    // 2^(3*MORT_BITS)

#define AUX_BLOCKS 1184     // 148 SMs x 8 — all co-resident at occ 8
#define R_A        5242880  // repack elems phase 1 (62.5%)  [R11 schedule]
#define R_B        (TBL_TOTAL - R_A)

// Static scratch (allocation-guard safe; zero-initialized at load):
__device__ float2 g_tbl[TBL_TOTAL];      // 64 MB feature-interleaved table
__device__ float4 g_xs[N_POINTS];        // 16 MB sorted points (.w = orig idx)
__device__ int    g_hist[NBUCK];         // histogram (zeroed in phase 2)
__device__ int    g_cursor[NBUCK];       // chunk-relative exclusive scan -> cursor
__device__ int    g_bsum[32];            // per-chunk totals
__device__ int           g_barcnt;       // grid barrier (self-resetting)
__device__ volatile int  g_bargen;       // generation (monotonic across replays)

struct ScalArr { float s[NUM_LEVELS]; };

// ---------------------------------------------------------------------------
// Software grid barrier: all AUX_BLOCKS are co-resident by construction.
// ---------------------------------------------------------------------------
__device__ __forceinline__ void grid_sync() {
    __syncthreads();
    if (threadIdx.x == 0) {
        __threadfence();
        int my = g_bargen;
        int old = atomicAdd(&g_barcnt, 1);
        if (old == AUX_BLOCKS - 1) {
            g_barcnt = 0;
            __threadfence();
            g_bargen = my + 1;
        } else {
            while (g_bargen == my) __nanosleep(64);
        }
    }
    __syncthreads();
}

// Scalar repack (R11 proven — quad variant regressed in R13/R14).
__device__ __forceinline__ void repack_one(const float* __restrict__ ht, int i) {
    float a = __ldg(ht + i);
    float b = __ldg(ht + i + TBL_TOTAL);
    g_tbl[i] = make_float2(a, b);
}

// ---------------------------------------------------------------------------
// Morton bucket (5 bits/dim -> 15-bit code)
// ---------------------------------------------------------------------------
__device__ __forceinline__ unsigned mort5(unsigned v) {
    unsigned m = 0;
    #pragma unroll
    for (int b = 0; b < MORT_BITS; ++b) m |= ((v >> b) & 1u) << (3 * b);
    return m;
}

__device__ __forceinline__ unsigned bucket_of(float x, float y, float z) {
    unsigned ix = min(31u, (unsigned)(int)(x * 32.0f));
    unsigned iy = min(31u, (unsigned)(int)(y * 32.0f));
    unsigned iz = min(31u, (unsigned)(int)(z * 32.0f));
    return mort5(ix) | (mort5(iy) << 1) | (mort5(iz) << 2);
}

// ---------------------------------------------------------------------------
// Persistent aux kernel: hist -> scan -> scatter; repack in phases 1+2.
// ---------------------------------------------------------------------------
__global__ __launch_bounds__(256, 8) void aux_kernel(const float* __restrict__ x,
                                                     const float* __restrict__ ht) {
    const int t    = threadIdx.x;
    const int gtid = blockIdx.x * 256 + t;
    const int GT   = AUX_BLOCKS * 256;

    __shared__ int s_w[8];
    __shared__ int s_boff[32];

    // ---- Phase 1: histogram + repack A ----
    for (int n = gtid; n < N_POINTS; n += GT) {
        float vx = x[3 * n + 0], vy = x[3 * n + 1], vz = x[3 * n + 2];
        atomicAdd(&g_hist[bucket_of(vx, vy, vz)], 1);
    }
    for (int i = gtid; i < R_A; i += GT) repack_one(ht, i);

    grid_sync();

    // ---- Phase 2: 32 blocks scan their 1024-bucket chunk; rest repack B ----
    if (blockIdx.x < 32) {
        int c = blockIdx.x;
        int base = c * 1024 + t * 4;
        int4 v = __ldcg((const int4*)&g_hist[base]);
        int tot = v.x + v.y + v.z + v.w;

        int lane = t & 31, w = t >> 5;
        int s = tot;
        #pragma unroll
        for (int off = 1; off < 32; off <<= 1) {
            int u = __shfl_up_sync(0xFFFFFFFF, s, off);
            if (lane >= off) s += u;
        }
        if (lane == 31) s_w[w] = s;
        __syncthreads();
        if (w == 0 && lane < 8) {
            int v8 = s_w[lane];
            int s8 = v8;
            #pragma unroll
            for (int off = 1; off < 8; off <<= 1) {
                int u = __shfl_up_sync(0xFF, s8, off);
                if (lane >= off) s8 += u;
            }
            s_w[lane] = s8 - v8;
        }
        __syncthreads();
        int run = s_w[w] + (s - tot);

        int4 cu;
        cu.x = run; run += v.x;
        cu.y = run; run += v.y;
        cu.z = run; run += v.z;
        cu.w = run; run += v.w;
        *(int4*)&g_cursor[base] = cu;
        *(int4*)&g_hist[base]   = make_int4(0, 0, 0, 0);
        if (t == 255) g_bsum[c] = run;
    } else {
        int gtid2 = (blockIdx.x - 32) * 256 + t;
        int GT2   = (AUX_BLOCKS - 32) * 256;
        for (int i = gtid2; i < R_B; i += GT2) repack_one(ht, R_A + i);
    }

    grid_sync();

    // ---- Phase 3: inline boff scan + scatter ----
    if (t < 32) {
        int v = __ldcg(&g_bsum[t]);
        int s = v;
        #pragma unroll
        for (int off = 1; off < 32; off <<= 1) {
            int u = __shfl_up_sync(0xFFFFFFFF, s, off);
            if (t >= off) s += u;
        }
        s_boff[t] = s - v;
    }
    __syncthreads();

    for (int n = gtid; n < N_POINTS; n += GT) {
        float vx = x[3 * n + 0], vy = x[3 * n + 1], vz = x[3 * n + 2];
        unsigned b = bucket_of(vx, vy, vz);
        int pos = s_boff[b >> 10] + atomicAdd(&g_cursor[b], 1);
        g_xs[pos] = make_float4(vx, vy, vz, __int_as_float(n));
    }
}

// ---------------------------------------------------------------------------
// Scrambled weight: fracflat[k] = frac( coord[k%3] * scaling[k/3] )
// ---------------------------------------------------------------------------
__device__ __forceinline__ float fracw(float vx, float vy, float vz,
                                       const float* __restrict__ s, int k) {
    int d = k % 3;
    float v = (d == 0) ? vx : ((d == 1) ? vy : vz);
    float t = v * s[k / 3];
    return t - floorf(t);
}

// ---------------------------------------------------------------------------
// Paired x-corner gather (R11 proven form). PRIMES[0]==1, so the two
// x-corners hash to i0 = fx^m, i1 = (fx+1)^m; when fx is even they are the
// two halves of ONE 16B-aligned float4 -> one load / one sector.
// ---------------------------------------------------------------------------
__device__ __forceinline__ void ld_xpair(const float2* __restrict__ tbl,
                                         unsigned fx, unsigned cx, unsigned m,
                                         float2& Ff, float2& Fc) {
    unsigned i0 = (fx ^ m) & HMASK;
    unsigned i1 = (cx ^ m) & HMASK;
    float4 q = __ldg((const float4*)(tbl + (i0 & ~1u)));
    float2 lo = make_float2(q.x, q.y);
    float2 hi = make_float2(q.z, q.w);
    Ff = (i0 & 1u) ? hi : lo;
    if ((i0 ^ i1) <= 1u) {
        Fc = (i1 & 1u) ? hi : lo;          // same aligned pair: free
    } else {
        Fc = __ldg(tbl + i1);              // predicated second load (~50% lanes)
    }
}

// One level: 4 paired gathers + scrambled trilinear blend -> 2 floats.
__device__ __forceinline__ void enc_level(float vx, float vy, float vz,
                                          const ScalArr& sc, int L,
                                          float& out0, float& out1) {
    float s  = sc.s[L];
    float sx = vx * s, sy = vy * s, sz = vz * s;

    unsigned fx = (unsigned)(int)floorf(sx);
    unsigned cx = (unsigned)(int)ceilf(sx);
    unsigned fy = (unsigned)(int)floorf(sy);
    unsigned cy = (unsigned)(int)ceilf(sy);
    unsigned fz = (unsigned)(int)floorf(sz);
    unsigned cz = (unsigned)(int)ceilf(sz);

    unsigned hyf = fy * P2, hyc = cy * P2;
    unsigned hzf = fz * P3, hzc = cz * P3;

    const float2* __restrict__ tbl = g_tbl + (size_t)L * TABLE_SIZE;

    float2 F0, F1, F2, F3, F4, F5, F6, F7;
    ld_xpair(tbl, fx, cx, hyc ^ hzc, F3, F0);
    ld_xpair(tbl, fx, cx, hyc ^ hzf, F5, F1);
    ld_xpair(tbl, fx, cx, hyf ^ hzc, F6, F2);
    ld_xpair(tbl, fx, cx, hyf ^ hzf, F7, F4);

    float wx = fracw(vx, vy, vz, sc.s, L);
    float wy = fracw(vx, vy, vz, sc.s, 16 + L);
    float wz = fracw(vx, vy, vz, sc.s, 32 + L);
    float qx = 1.0f - wx, qy = 1.0f - wy, qz = 1.0f - wz;

    {
        float f03 = F0.x * wx + F3.x * qx;
        float f12 = F1.x * wx + F2.x * qx;
        float f56 = F5.x * wx + F6.x * qx;
        float f47 = F4.x * wx + F7.x * qx;
        float a   = f03 * wy + f12 * qy;
        float b   = f47 * wy + f56 * qy;
        out0 = a * wz + b * qz;
    }
    {
        float f03 = F0.y * wx + F3.y * qx;
        float f12 = F1.y * wx + F2.y * qx;
        float f56 = F5.y * wx + F6.y * qx;
        float f47 = F4.y * wx + F7.y * qx;
        float a   = f03 * wy + f12 * qy;
        float b   = f47 * wy + f56 * qy;
        out1 = a * wz + b * qz;
    }
}

// ---------------------------------------------------------------------------
// Main encoding kernel: one thread per (Morton-sorted) point.
// ---------------------------------------------------------------------------
__global__ __launch_bounds__(256, 4) void hashenc_kernel(
    float* __restrict__ out,
    ScalArr sc)
{
    int n = blockIdx.x * blockDim.x + threadIdx.x;

    float4 p = g_xs[n];
    float vx = p.x, vy = p.y, vz = p.z;
    int orig = __float_as_int(p.w);

    float4* o = (float4*)(out + (size_t)orig * (2 * NUM_LEVELS));

    #pragma unroll
    for (int Lp = 0; Lp < NUM_LEVELS / 2; ++Lp) {
        float4 r;
        enc_level(vx, vy, vz, sc, 2 * Lp + 0, r.x, r.y);
        enc_level(vx, vy, vz, sc, 2 * Lp + 1, r.z, r.w);
        o[Lp] = r;
    }
}

// ---------------------------------------------------------------------------
// Host: replicate numpy's SCALINGS bit-for-bit with double libm.
// ---------------------------------------------------------------------------
static void compute_scalings(ScalArr& a) {
    double growth = exp((log(2048.0) - log(16.0)) / 15.0);
    for (int l = 0; l < NUM_LEVELS; ++l)
        a.s[l] = (float)floor(16.0 * pow(growth, (double)l));
}

extern "C" void kernel_launch(void* const* d_in, const int* in_sizes, int n_in,
                              void* d_out, int out_size) {
    const float* x  = (const float*)d_in[0];
    const float* ht = (const float*)d_in[1];
    float* out = (float*)d_out;

    ScalArr sc;
    compute_scalings(sc);

    aux_kernel<<<AUX_BLOCKS, 256>>>(x, ht);
    hashenc_kernel<<<N_POINTS / 256, 256>>>(out, sc);
}